// round 2
// baseline (speedup 1.0000x reference)
#include <cuda_runtime.h>
#include <cuda_bf16.h>

// ---------------------------------------------------------------------------
// VQ-VAE forward, fp32, packed-f32x2 FFMA2 GEMMs (Blackwell dual-issue fp32).
// ---------------------------------------------------------------------------

#define M_ROWS 8192
#define EMB_NUM 1024
#define EMB_DIM 64

typedef unsigned long long u64;

__device__ __forceinline__ u64 pack2(float lo, float hi) {
    u64 r;
    asm("mov.b64 %0, {%1, %2};" : "=l"(r) : "f"(lo), "f"(hi));
    return r;
}
__device__ __forceinline__ void unpack2(u64 v, float& lo, float& hi) {
    asm("mov.b64 {%0, %1}, %2;" : "=f"(lo), "=f"(hi) : "l"(v));
}
__device__ __forceinline__ u64 ffma2(u64 a, u64 b, u64 c) {
    u64 d;
    asm("fma.rn.f32x2 %0, %1, %2, %3;" : "=l"(d) : "l"(a), "l"(b), "l"(c));
    return d;
}

// Scratch (static device globals -- allocation-free rule)
__device__ float g_h1[8192 * 1024];
__device__ float g_h2[8192 * 512];
__device__ float g_z [8192 * 256];
__device__ float g_zq[8192 * 256];
__device__ float g_d1[8192 * 512];
__device__ float g_d2[8192 * 1024];
__device__ float g_cn[EMB_NUM];

// ---------------------------------------------------------------------------
// Tiled SGEMM: C[M,N] = A[M,K] @ W[N,K]^T + bias[N], optional ReLU.
// Inner product via packed fma.rn.f32x2 (bit-exact fp32, 2x FFMA rate).
// Requires: M % BM == 0, N % BN == 0, K % BK == 0 (true for all shapes here).
// ---------------------------------------------------------------------------
template <int BM, int BN, int BK, int TM, int TN, bool RELU>
__global__ __launch_bounds__((BM / TM) * (BN / TN), 2)
void gemm_bias_kernel(const float* __restrict__ A,
                      const float* __restrict__ W,
                      const float* __restrict__ bias,
                      float* __restrict__ C,
                      int M, int N, int K) {
    constexpr int THREADS = (BM / TM) * (BN / TN);
    constexpr int PAD = 4;
    __shared__ float As[BK][BM + PAD];
    __shared__ float Ws[BK][BN + PAD];

    const int bm = blockIdx.y * BM;
    const int bn = blockIdx.x * BN;
    const int tid = threadIdx.x;
    const int tx = tid % (BN / TN);   // 0..15
    const int ty = tid / (BN / TN);   // 0..15

    u64 accP[TM][TN / 2];
#pragma unroll
    for (int i = 0; i < TM; i++)
#pragma unroll
        for (int j = 0; j < TN / 2; j++) accP[i][j] = 0ull;

    for (int k0 = 0; k0 < K; k0 += BK) {
        // Load A tile (BM x BK) transposed into As[BK][BM]
#pragma unroll
        for (int i = tid; i < BM * BK / 4; i += THREADS) {
            int r  = i / (BK / 4);
            int c4 = i % (BK / 4);
            float4 v = *reinterpret_cast<const float4*>(A + (size_t)(bm + r) * K + k0 + c4 * 4);
            As[c4 * 4 + 0][r] = v.x;
            As[c4 * 4 + 1][r] = v.y;
            As[c4 * 4 + 2][r] = v.z;
            As[c4 * 4 + 3][r] = v.w;
        }
        // Load W tile (BN x BK) transposed into Ws[BK][BN]
#pragma unroll
        for (int i = tid; i < BN * BK / 4; i += THREADS) {
            int r  = i / (BK / 4);
            int c4 = i % (BK / 4);
            float4 v = *reinterpret_cast<const float4*>(W + (size_t)(bn + r) * K + k0 + c4 * 4);
            Ws[c4 * 4 + 0][r] = v.x;
            Ws[c4 * 4 + 1][r] = v.y;
            Ws[c4 * 4 + 2][r] = v.z;
            Ws[c4 * 4 + 3][r] = v.w;
        }
        __syncthreads();

#pragma unroll
        for (int k = 0; k < BK; k++) {
            float4 a0 = *reinterpret_cast<const float4*>(&As[k][ty * TM + 0]);
            float4 a1 = *reinterpret_cast<const float4*>(&As[k][ty * TM + 4]);
            float4 b0 = *reinterpret_cast<const float4*>(&Ws[k][tx * TN + 0]);
            float4 b1 = *reinterpret_cast<const float4*>(&Ws[k][tx * TN + 4]);

            u64 bP[TN / 2];
            bP[0] = pack2(b0.x, b0.y);
            bP[1] = pack2(b0.z, b0.w);
            bP[2] = pack2(b1.x, b1.y);
            bP[3] = pack2(b1.z, b1.w);

            u64 aP[TM];
            aP[0] = pack2(a0.x, a0.x);
            aP[1] = pack2(a0.y, a0.y);
            aP[2] = pack2(a0.z, a0.z);
            aP[3] = pack2(a0.w, a0.w);
            aP[4] = pack2(a1.x, a1.x);
            aP[5] = pack2(a1.y, a1.y);
            aP[6] = pack2(a1.z, a1.z);
            aP[7] = pack2(a1.w, a1.w);

#pragma unroll
            for (int i = 0; i < TM; i++)
#pragma unroll
                for (int j = 0; j < TN / 2; j++)
                    accP[i][j] = ffma2(aP[i], bP[j], accP[i][j]);
        }
        __syncthreads();
    }

    // Epilogue: unpack, bias (+ ReLU), vectorized stores
    float bv[TN];
#pragma unroll
    for (int j = 0; j < TN; j++) bv[j] = bias[bn + tx * TN + j];

#pragma unroll
    for (int i = 0; i < TM; i++) {
        int row = bm + ty * TM + i;
        float out[TN];
#pragma unroll
        for (int j = 0; j < TN / 2; j++) {
            float lo, hi;
            unpack2(accP[i][j], lo, hi);
            float v0 = lo + bv[j * 2 + 0];
            float v1 = hi + bv[j * 2 + 1];
            if (RELU) { v0 = fmaxf(v0, 0.0f); v1 = fmaxf(v1, 0.0f); }
            out[j * 2 + 0] = v0;
            out[j * 2 + 1] = v1;
        }
        float* cptr = C + (size_t)row * N + bn + tx * TN;
        *reinterpret_cast<float4*>(cptr + 0) = *reinterpret_cast<float4*>(&out[0]);
        *reinterpret_cast<float4*>(cptr + 4) = *reinterpret_cast<float4*>(&out[4]);
    }
}

// ---------------------------------------------------------------------------
// Codebook squared norms: cn[i] = sum_d codebook[i][d]^2
// ---------------------------------------------------------------------------
__global__ void cnorm_kernel(const float* __restrict__ cb, float* __restrict__ cn) {
    int i = blockIdx.x * blockDim.x + threadIdx.x;
    if (i >= EMB_NUM) return;
    const float4* p = reinterpret_cast<const float4*>(cb + (size_t)i * EMB_DIM);
    float s = 0.0f;
#pragma unroll
    for (int d = 0; d < EMB_DIM / 4; d++) {
        float4 v = p[d];
        s += v.x * v.x + v.y * v.y + v.z * v.z + v.w * v.w;
    }
    cn[i] = s;
}

// ---------------------------------------------------------------------------
// Vector quantization: one thread per 64-dim row (32768 rows).
// dist(j) = ||c_j||^2 + (-2 z) . c_j  via packed f32x2 FMA (halves summed at
// end; only feeds argmin). First minimum kept (strict <) to match jnp.argmin.
// ---------------------------------------------------------------------------
__global__ __launch_bounds__(256)
void vq_kernel(const float* __restrict__ z,
               const float* __restrict__ cb,
               const float* __restrict__ cn,
               float* __restrict__ zq) {
    constexpr int CHUNK = 128;
    __shared__ float sc[CHUNK][EMB_DIM];
    __shared__ float scn[CHUNK];

    const int row = blockIdx.x * blockDim.x + threadIdx.x;  // 0..32767
    const float* zp = z + (size_t)row * EMB_DIM;

    u64 m2zP[EMB_DIM / 2];  // packed pairs of -2*z
#pragma unroll
    for (int d = 0; d < EMB_DIM / 4; d++) {
        float4 v = reinterpret_cast<const float4*>(zp)[d];
        m2zP[d * 2 + 0] = pack2(-2.0f * v.x, -2.0f * v.y);
        m2zP[d * 2 + 1] = pack2(-2.0f * v.z, -2.0f * v.w);
    }

    float best = 3.0e38f;
    int bidx = 0;

    for (int ch = 0; ch < EMB_NUM / CHUNK; ch++) {
        __syncthreads();
        const float4* src = reinterpret_cast<const float4*>(cb + (size_t)ch * CHUNK * EMB_DIM);
        float4* dst = reinterpret_cast<float4*>(&sc[0][0]);
#pragma unroll
        for (int i = threadIdx.x; i < CHUNK * EMB_DIM / 4; i += 256) dst[i] = src[i];
        if (threadIdx.x < CHUNK) scn[threadIdx.x] = cn[ch * CHUNK + threadIdx.x];
        __syncthreads();

        for (int j = 0; j < CHUNK; j++) {
            u64 sP = 0ull;
#pragma unroll
            for (int d = 0; d < EMB_DIM / 4; d++) {
                float4 c = reinterpret_cast<const float4*>(&sc[j][0])[d];
                sP = ffma2(pack2(c.x, c.y), m2zP[d * 2 + 0], sP);
                sP = ffma2(pack2(c.z, c.w), m2zP[d * 2 + 1], sP);
            }
            float lo, hi;
            unpack2(sP, lo, hi);
            float s = scn[j] + lo + hi;
            int gidx = ch * CHUNK + j;
            if (s < best) { best = s; bidx = gidx; }
        }
    }

    // gather + straight-through: out = z + (c - z)
    const float4* cp = reinterpret_cast<const float4*>(cb + (size_t)bidx * EMB_DIM);
    const float4* zp4 = reinterpret_cast<const float4*>(zp);
    float4* op = reinterpret_cast<float4*>(zq + (size_t)row * EMB_DIM);
#pragma unroll
    for (int d = 0; d < EMB_DIM / 4; d++) {
        float4 c = cp[d], zz = zp4[d], o;
        o.x = zz.x + (c.x - zz.x);
        o.y = zz.y + (c.y - zz.y);
        o.z = zz.z + (c.z - zz.z);
        o.w = zz.w + (c.w - zz.w);
        op[d] = o;
    }
}

// ---------------------------------------------------------------------------
// Launch
// ---------------------------------------------------------------------------
static inline void launch_gemm(const float* A, const float* W, const float* b,
                               float* C, int M, int N, int K, bool relu,
                               cudaStream_t s) {
    dim3 grid(N / 128, M / 128);
    if (relu)
        gemm_bias_kernel<128, 128, 16, 8, 8, true ><<<grid, 256, 0, s>>>(A, W, b, C, M, N, K);
    else
        gemm_bias_kernel<128, 128, 16, 8, 8, false><<<grid, 256, 0, s>>>(A, W, b, C, M, N, K);
}

extern "C" void kernel_launch(void* const* d_in, const int* in_sizes, int n_in,
                              void* d_out, int out_size) {
    const float* x        = (const float*)d_in[0];
    const float* enc0_w   = (const float*)d_in[1];
    const float* enc0_b   = (const float*)d_in[2];
    const float* enc1_w   = (const float*)d_in[3];
    const float* enc1_b   = (const float*)d_in[4];
    const float* z_w      = (const float*)d_in[5];
    const float* z_b      = (const float*)d_in[6];
    const float* codebook = (const float*)d_in[7];
    const float* dec0_w   = (const float*)d_in[8];
    const float* dec0_b   = (const float*)d_in[9];
    const float* dec1_w   = (const float*)d_in[10];
    const float* dec1_b   = (const float*)d_in[11];
    const float* out_w    = (const float*)d_in[12];
    const float* out_b    = (const float*)d_in[13];
    float* out = (float*)d_out;

    float *h1, *h2, *z, *zq, *d1, *d2, *cn;
    cudaGetSymbolAddress((void**)&h1, g_h1);
    cudaGetSymbolAddress((void**)&h2, g_h2);
    cudaGetSymbolAddress((void**)&z,  g_z);
    cudaGetSymbolAddress((void**)&zq, g_zq);
    cudaGetSymbolAddress((void**)&d1, g_d1);
    cudaGetSymbolAddress((void**)&d2, g_d2);
    cudaGetSymbolAddress((void**)&cn, g_cn);

    cudaStream_t s = 0;

    // encoder
    launch_gemm(x,  enc0_w, enc0_b, h1, M_ROWS, 1024, 2048, true,  s);
    launch_gemm(h1, enc1_w, enc1_b, h2, M_ROWS, 512,  1024, true,  s);
    launch_gemm(h2, z_w,    z_b,    z,  M_ROWS, 256,  512,  false, s);

    // vector quantization
    cnorm_kernel<<<4, 256, 0, s>>>(codebook, cn);
    vq_kernel<<<(M_ROWS * 256 / EMB_DIM) / 256, 256, 0, s>>>(z, codebook, cn, zq);

    // decoder
    launch_gemm(zq, dec0_w, dec0_b, d1, M_ROWS, 512,  256,  true,  s);
    launch_gemm(d1, dec1_w, dec1_b, d2, M_ROWS, 1024, 512,  true,  s);
    launch_gemm(d2, out_w,  out_b,  out, M_ROWS, 2048, 1024, false, s);
}

// round 6
// speedup vs baseline: 1.1479x; 1.1479x over previous
#include <cuda_runtime.h>
#include <cuda_bf16.h>
#include <cstdint>

// ===========================================================================
// VQ-VAE forward on GB300:
//   encoder  : exact fp32 SIMT GEMMs (argmin-critical; proven rel_err 0.0)
//   VQ       : fp32 distances (round-1 code), outputs zq as 2 bf16 planes
//   decoder  : bf16 HMMA (mma.sync m16n8k16), 2-plane / 3-product emulation
//              (hh + hm + mh; error ~1e-5 << 1e-3 tolerance)
// ===========================================================================

#define M_ROWS 8192
#define EMB_NUM 1024
#define EMB_DIM 64

typedef unsigned long long u64;
typedef __nv_bfloat16 bf16;

// ---------------------------------------------------------------------------
// Static device scratch (allocation-free rule)
// ---------------------------------------------------------------------------
__device__ float g_h1[8192 * 1024];
__device__ float g_h2[8192 * 512];
__device__ float g_z [8192 * 256];
__device__ float g_cn[EMB_NUM];
__device__ bf16 g_zq[2][8192 * 256];
__device__ bf16 g_d1[2][8192 * 512];
__device__ bf16 g_d2[2][8192 * 1024];
__device__ bf16 g_wd0[2][512 * 256];
__device__ bf16 g_wd1[2][1024 * 512];
__device__ bf16 g_wo[2][2048 * 1024];

// ---------------------------------------------------------------------------
// PTX helpers
// ---------------------------------------------------------------------------
__device__ __forceinline__ uint32_t smem_u32(const void* p) {
    uint32_t a;
    asm("{ .reg .u64 t; cvta.to.shared.u64 t, %1; cvt.u32.u64 %0, t; }" : "=r"(a) : "l"(p));
    return a;
}
__device__ __forceinline__ void cp16(uint32_t dst, const void* src) {
    asm volatile("cp.async.cg.shared.global [%0], [%1], 16;" :: "r"(dst), "l"(src));
}
#define CP_COMMIT() asm volatile("cp.async.commit_group;" ::: "memory")
#define CP_WAIT0()  asm volatile("cp.async.wait_group 0;" ::: "memory")

__device__ __forceinline__ void ldm_x4(uint32_t r[4], uint32_t addr) {
    asm volatile("ldmatrix.sync.aligned.m8n8.x4.shared.b16 {%0,%1,%2,%3}, [%4];"
                 : "=r"(r[0]), "=r"(r[1]), "=r"(r[2]), "=r"(r[3]) : "r"(addr));
}
__device__ __forceinline__ void mma_bf16(float* d, const uint32_t* a, uint32_t b0, uint32_t b1) {
    asm volatile(
        "mma.sync.aligned.m16n8k16.row.col.f32.bf16.bf16.f32 "
        "{%0,%1,%2,%3}, {%4,%5,%6,%7}, {%8,%9}, {%0,%1,%2,%3};"
        : "+f"(d[0]), "+f"(d[1]), "+f"(d[2]), "+f"(d[3])
        : "r"(a[0]), "r"(a[1]), "r"(a[2]), "r"(a[3]), "r"(b0), "r"(b1));
}

// ---------------------------------------------------------------------------
// ENCODER: exact fp32 tiled SGEMM (round-1 code, rel_err 0.0 verified)
// C[M,N] = A[M,K] @ W[N,K]^T + bias, optional ReLU.
// ---------------------------------------------------------------------------
template <int BM, int BN, int BK, int TM, int TN, bool RELU>
__global__ __launch_bounds__((BM / TM) * (BN / TN))
void gemm_bias_kernel(const float* __restrict__ A,
                      const float* __restrict__ W,
                      const float* __restrict__ bias,
                      float* __restrict__ C,
                      int M, int N, int K) {
    constexpr int THREADS = (BM / TM) * (BN / TN);
    constexpr int PAD = 4;
    __shared__ float As[BK][BM + PAD];
    __shared__ float Ws[BK][BN + PAD];

    const int bm = blockIdx.y * BM;
    const int bn = blockIdx.x * BN;
    const int tid = threadIdx.x;
    const int tx = tid % (BN / TN);
    const int ty = tid / (BN / TN);

    float acc[TM][TN];
#pragma unroll
    for (int i = 0; i < TM; i++)
#pragma unroll
        for (int j = 0; j < TN; j++) acc[i][j] = 0.0f;

    for (int k0 = 0; k0 < K; k0 += BK) {
#pragma unroll
        for (int i = tid; i < BM * BK / 4; i += THREADS) {
            int r  = i / (BK / 4);
            int c4 = i % (BK / 4);
            float4 v = *reinterpret_cast<const float4*>(A + (size_t)(bm + r) * K + k0 + c4 * 4);
            As[c4 * 4 + 0][r] = v.x;
            As[c4 * 4 + 1][r] = v.y;
            As[c4 * 4 + 2][r] = v.z;
            As[c4 * 4 + 3][r] = v.w;
        }
#pragma unroll
        for (int i = tid; i < BN * BK / 4; i += THREADS) {
            int r  = i / (BK / 4);
            int c4 = i % (BK / 4);
            float4 v = *reinterpret_cast<const float4*>(W + (size_t)(bn + r) * K + k0 + c4 * 4);
            Ws[c4 * 4 + 0][r] = v.x;
            Ws[c4 * 4 + 1][r] = v.y;
            Ws[c4 * 4 + 2][r] = v.z;
            Ws[c4 * 4 + 3][r] = v.w;
        }
        __syncthreads();

#pragma unroll
        for (int k = 0; k < BK; k++) {
            float a[TM], b[TN];
            *reinterpret_cast<float4*>(&a[0]) = *reinterpret_cast<const float4*>(&As[k][ty * TM + 0]);
            *reinterpret_cast<float4*>(&a[4]) = *reinterpret_cast<const float4*>(&As[k][ty * TM + 4]);
            *reinterpret_cast<float4*>(&b[0]) = *reinterpret_cast<const float4*>(&Ws[k][tx * TN + 0]);
            *reinterpret_cast<float4*>(&b[4]) = *reinterpret_cast<const float4*>(&Ws[k][tx * TN + 4]);
#pragma unroll
            for (int i = 0; i < TM; i++)
#pragma unroll
                for (int j = 0; j < TN; j++)
                    acc[i][j] = fmaf(a[i], b[j], acc[i][j]);
        }
        __syncthreads();
    }

    float bv[TN];
#pragma unroll
    for (int j = 0; j < TN; j++) bv[j] = bias[bn + tx * TN + j];

#pragma unroll
    for (int i = 0; i < TM; i++) {
        int row = bm + ty * TM + i;
        float out[TN];
#pragma unroll
        for (int j = 0; j < TN; j++) {
            float v = acc[i][j] + bv[j];
            if (RELU) v = fmaxf(v, 0.0f);
            out[j] = v;
        }
        float* cptr = C + (size_t)row * N + bn + tx * TN;
        *reinterpret_cast<float4*>(cptr + 0) = *reinterpret_cast<float4*>(&out[0]);
        *reinterpret_cast<float4*>(cptr + 4) = *reinterpret_cast<float4*>(&out[4]);
    }
}

// ---------------------------------------------------------------------------
// DECODER: bf16 HMMA GEMM, 2-plane inputs, 3 products (hh, hm, mh).
// CTA 128x128, 8 warps (2M x 4N), warp 64x32, BK=32, double buffer.
// OUTP: 0 = fp32 out, 2 = bf16 2-plane out. Split accumulators.
// ---------------------------------------------------------------------------
template <bool RELU, int OUTP>
__global__ __launch_bounds__(256)
void gemm_hmma_kernel(const bf16* __restrict__ A0, const bf16* __restrict__ A1,
                      const bf16* __restrict__ B0, const bf16* __restrict__ B1,
                      const float* __restrict__ bias,
                      float* __restrict__ Cf,
                      bf16* __restrict__ Ch, bf16* __restrict__ Cm,
                      int N, int K, int kcShift) {
    __shared__ alignas(128) bf16 As[2][128 * 40];
    __shared__ alignas(128) bf16 Bs[2][128 * 40];

    const int tid = threadIdx.x;
    const int wid = tid >> 5, lane = tid & 31;
    const int wm = wid >> 2, wn = wid & 3;
    const int bn = blockIdx.x * 128, bm = blockIdx.y * 128;
    const int KC = K >> 5;
    const int NC = 3 * KC;   // products: (0,0) (0,1) (1,0)

    const bf16* Arow0 = A0 + (size_t)bm * K;
    const bf16* Arow1 = A1 + (size_t)bm * K;
    const bf16* Brow0 = B0 + (size_t)bn * K;
    const bf16* Brow1 = B1 + (size_t)bn * K;

    const uint32_t sAu = smem_u32(As), sBu = smem_u32(Bs);
    const uint32_t STG = 128 * 40 * 2;

    float accM[4][4][4], accC[4][4][4];
#pragma unroll
    for (int i = 0; i < 4; i++)
#pragma unroll
        for (int j = 0; j < 4; j++)
#pragma unroll
            for (int q = 0; q < 4; q++) { accM[i][j][q] = 0.0f; accC[i][j][q] = 0.0f; }

    auto chunk_desc = [&](int c, const bf16*& a, const bf16*& b, int& k0) {
        int ph = c >> kcShift;            // 0,1,2
        k0 = (c & (KC - 1)) << 5;
        a = (ph >= 2) ? Arow1 : Arow0;
        b = (ph == 1) ? Brow1 : Brow0;
    };

    auto load_tile = [&](int buf, const bf16* a, const bf16* b, int k0) {
#pragma unroll
        for (int i = 0; i < 2; i++) {
            int ch = tid * 2 + i;
            int r = ch >> 2, cc = ch & 3;
            uint32_t so = (uint32_t)(buf * STG + r * 80 + cc * 16);
            cp16(sAu + so, a + (size_t)r * K + k0 + cc * 8);
            cp16(sBu + so, b + (size_t)r * K + k0 + cc * 8);
        }
        CP_COMMIT();
    };

    { const bf16 *a, *b; int k0; chunk_desc(0, a, b, k0); load_tile(0, a, b, k0); }

    for (int c = 0; c < NC; c++) {
        CP_WAIT0();
        __syncthreads();
        if (c + 1 < NC) {
            const bf16 *a, *b; int k0;
            chunk_desc(c + 1, a, b, k0);
            load_tile((c + 1) & 1, a, b, k0);
        }
        const uint32_t sa = sAu + (c & 1) * STG;
        const uint32_t sb = sBu + (c & 1) * STG;
        const bool isMain = (c >> kcShift) == 0;
#pragma unroll
        for (int ks = 0; ks < 2; ks++) {
            uint32_t af[4][4], bg[2][4];
#pragma unroll
            for (int mt = 0; mt < 4; mt++) {
                uint32_t addr = sa + (uint32_t)((wm * 64 + mt * 16 + ((lane >> 3) & 1) * 8 + (lane & 7)) * 80
                                                + (ks * 16 + (lane >> 4) * 8) * 2);
                ldm_x4(af[mt], addr);
            }
#pragma unroll
            for (int np = 0; np < 2; np++) {
                uint32_t addr = sb + (uint32_t)((wn * 32 + np * 16 + ((lane >> 4) & 1) * 8 + (lane & 7)) * 80
                                                + (ks * 16 + ((lane >> 3) & 1) * 8) * 2);
                ldm_x4(bg[np], addr);
            }
            if (isMain) {
#pragma unroll
                for (int mt = 0; mt < 4; mt++)
#pragma unroll
                    for (int nt = 0; nt < 4; nt++)
                        mma_bf16(accM[mt][nt], af[mt], bg[nt >> 1][(nt & 1) * 2], bg[nt >> 1][(nt & 1) * 2 + 1]);
            } else {
#pragma unroll
                for (int mt = 0; mt < 4; mt++)
#pragma unroll
                    for (int nt = 0; nt < 4; nt++)
                        mma_bf16(accC[mt][nt], af[mt], bg[nt >> 1][(nt & 1) * 2], bg[nt >> 1][(nt & 1) * 2 + 1]);
            }
        }
        __syncthreads();
    }

#pragma unroll
    for (int mt = 0; mt < 4; mt++) {
#pragma unroll
        for (int nt = 0; nt < 4; nt++) {
            const int r0 = bm + wm * 64 + mt * 16 + (lane >> 2);
            const int c0 = bn + wn * 32 + nt * 8 + (lane & 3) * 2;
            const float bv0 = bias[c0], bv1 = bias[c0 + 1];
#pragma unroll
            for (int h = 0; h < 2; h++) {
                const int r = r0 + h * 8;
                float v0 = (accM[mt][nt][h * 2 + 0] + accC[mt][nt][h * 2 + 0]) + bv0;
                float v1 = (accM[mt][nt][h * 2 + 1] + accC[mt][nt][h * 2 + 1]) + bv1;
                if (RELU) { v0 = fmaxf(v0, 0.0f); v1 = fmaxf(v1, 0.0f); }
                const size_t o = (size_t)r * N + c0;
                if (OUTP == 0) {
                    *reinterpret_cast<float2*>(Cf + o) = make_float2(v0, v1);
                } else {
                    bf16 h0 = __float2bfloat16(v0), h1v = __float2bfloat16(v1);
                    float r0f = v0 - __bfloat162float(h0);
                    float r1f = v1 - __bfloat162float(h1v);
                    __nv_bfloat162 hp; hp.x = h0; hp.y = h1v;
                    __nv_bfloat162 mp; mp.x = __float2bfloat16(r0f); mp.y = __float2bfloat16(r1f);
                    *reinterpret_cast<__nv_bfloat162*>(Ch + o) = hp;
                    *reinterpret_cast<__nv_bfloat162*>(Cm + o) = mp;
                }
            }
        }
    }
}

// ---------------------------------------------------------------------------
// fp32 -> 2 bf16 planes (decoder weights)
// ---------------------------------------------------------------------------
__global__ void split2_kernel(const float* __restrict__ src,
                              bf16* __restrict__ h, bf16* __restrict__ m, int n) {
    int i = blockIdx.x * blockDim.x + threadIdx.x;
    if (i < n) {
        float v = src[i];
        bf16 a = __float2bfloat16(v);
        float r1 = v - __bfloat162float(a);
        h[i] = a; m[i] = __float2bfloat16(r1);
    }
}

// ---------------------------------------------------------------------------
// Codebook squared norms
// ---------------------------------------------------------------------------
__global__ void cnorm_kernel(const float* __restrict__ cb, float* __restrict__ cn) {
    int i = blockIdx.x * blockDim.x + threadIdx.x;
    if (i >= EMB_NUM) return;
    const float4* p = reinterpret_cast<const float4*>(cb + (size_t)i * EMB_DIM);
    float s = 0.0f;
#pragma unroll
    for (int d = 0; d < EMB_DIM / 4; d++) {
        float4 v = p[d];
        s += v.x * v.x + v.y * v.y + v.z * v.z + v.w * v.w;
    }
    cn[i] = s;
}

// ---------------------------------------------------------------------------
// VQ: fp32 distances (round-1 code, verified). Outputs zq as 2 bf16 planes.
// ---------------------------------------------------------------------------
__device__ __forceinline__ u64 pack2f(float lo, float hi) {
    u64 r; asm("mov.b64 %0, {%1, %2};" : "=l"(r) : "f"(lo), "f"(hi)); return r;
}
__device__ __forceinline__ void unpack2f(u64 v, float& lo, float& hi) {
    asm("mov.b64 {%0, %1}, %2;" : "=f"(lo), "=f"(hi) : "l"(v));
}
__device__ __forceinline__ u64 ffma2(u64 a, u64 b, u64 c) {
    u64 d; asm("fma.rn.f32x2 %0, %1, %2, %3;" : "=l"(d) : "l"(a), "l"(b), "l"(c)); return d;
}

__global__ __launch_bounds__(256)
void vq_kernel(const float* __restrict__ z,
               const float* __restrict__ cb,
               const float* __restrict__ cn,
               bf16* __restrict__ qh, bf16* __restrict__ qm) {
    constexpr int CHUNK = 128;
    __shared__ float sc[CHUNK][EMB_DIM];
    __shared__ float scn[CHUNK];

    const int row = blockIdx.x * blockDim.x + threadIdx.x;
    const float* zp = z + (size_t)row * EMB_DIM;

    u64 m2zP[EMB_DIM / 2];
#pragma unroll
    for (int d = 0; d < EMB_DIM / 4; d++) {
        float4 v = reinterpret_cast<const float4*>(zp)[d];
        m2zP[d * 2 + 0] = pack2f(-2.0f * v.x, -2.0f * v.y);
        m2zP[d * 2 + 1] = pack2f(-2.0f * v.z, -2.0f * v.w);
    }

    float best = 3.0e38f;
    int bidx = 0;
    for (int ch = 0; ch < EMB_NUM / CHUNK; ch++) {
        __syncthreads();
        const float4* src = reinterpret_cast<const float4*>(cb + (size_t)ch * CHUNK * EMB_DIM);
        float4* dst = reinterpret_cast<float4*>(&sc[0][0]);
        for (int i = threadIdx.x; i < CHUNK * EMB_DIM / 4; i += 256) dst[i] = src[i];
        if (threadIdx.x < CHUNK) scn[threadIdx.x] = cn[ch * CHUNK + threadIdx.x];
        __syncthreads();

        for (int j = 0; j < CHUNK; j++) {
            u64 sP = 0ull;
#pragma unroll
            for (int d = 0; d < EMB_DIM / 4; d++) {
                float4 cc = reinterpret_cast<const float4*>(&sc[j][0])[d];
                sP = ffma2(pack2f(cc.x, cc.y), m2zP[d * 2 + 0], sP);
                sP = ffma2(pack2f(cc.z, cc.w), m2zP[d * 2 + 1], sP);
            }
            float lo, hi;
            unpack2f(sP, lo, hi);
            float s = scn[j] + lo + hi;
            if (s < best) { best = s; bidx = ch * CHUNK + j; }
        }
    }

    // STE fp32 replay: v = z + (c - z); split to 2 planes for decoder.
    const float* cp = cb + (size_t)bidx * EMB_DIM;
#pragma unroll
    for (int d = 0; d < EMB_DIM; d++) {
        float zz = zp[d];
        float v = zz + (cp[d] - zz);
        bf16 a = __float2bfloat16(v);
        float r1 = v - __bfloat162float(a);
        size_t o = (size_t)row * EMB_DIM + d;
        qh[o] = a; qm[o] = __float2bfloat16(r1);
    }
}

// ---------------------------------------------------------------------------
// Host launch
// ---------------------------------------------------------------------------
static inline int ilog2i(int v) { int s = 0; while ((1 << s) < v) s++; return s; }

static inline void launch_enc(const float* A, const float* W, const float* b,
                              float* C, int N, int K, bool relu) {
    dim3 grid(N / 128, M_ROWS / 128);
    if (relu)
        gemm_bias_kernel<128, 128, 16, 8, 8, true ><<<grid, 256>>>(A, W, b, C, M_ROWS, N, K);
    else
        gemm_bias_kernel<128, 128, 16, 8, 8, false><<<grid, 256>>>(A, W, b, C, M_ROWS, N, K);
}

template <bool RELU, int OUTP>
static inline void launch_dec(const bf16* A0, const bf16* A1,
                              const bf16* B0, const bf16* B1,
                              const float* bias, float* Cf, bf16* Ch, bf16* Cm,
                              int N, int K) {
    dim3 grid(N / 128, M_ROWS / 128);
    gemm_hmma_kernel<RELU, OUTP><<<grid, 256>>>(A0, A1, B0, B1, bias, Cf, Ch, Cm,
                                                N, K, ilog2i(K / 32));
}

extern "C" void kernel_launch(void* const* d_in, const int* in_sizes, int n_in,
                              void* d_out, int out_size) {
    const float* x        = (const float*)d_in[0];
    const float* enc0_w   = (const float*)d_in[1];
    const float* enc0_b   = (const float*)d_in[2];
    const float* enc1_w   = (const float*)d_in[3];
    const float* enc1_b   = (const float*)d_in[4];
    const float* z_w      = (const float*)d_in[5];
    const float* z_b      = (const float*)d_in[6];
    const float* codebook = (const float*)d_in[7];
    const float* dec0_w   = (const float*)d_in[8];
    const float* dec0_b   = (const float*)d_in[9];
    const float* dec1_w   = (const float*)d_in[10];
    const float* dec1_b   = (const float*)d_in[11];
    const float* out_w    = (const float*)d_in[12];
    const float* out_b    = (const float*)d_in[13];
    float* out = (float*)d_out;

    float *h1, *h2, *z, *cn;
    cudaGetSymbolAddress((void**)&h1, g_h1);
    cudaGetSymbolAddress((void**)&h2, g_h2);
    cudaGetSymbolAddress((void**)&z,  g_z);
    cudaGetSymbolAddress((void**)&cn, g_cn);
    bf16 (*zq)[8192 * 256];   cudaGetSymbolAddress((void**)&zq, g_zq);
    bf16 (*d1)[8192 * 512];   cudaGetSymbolAddress((void**)&d1, g_d1);
    bf16 (*d2)[8192 * 1024];  cudaGetSymbolAddress((void**)&d2, g_d2);
    bf16 (*wd0)[512 * 256];   cudaGetSymbolAddress((void**)&wd0, g_wd0);
    bf16 (*wd1)[1024 * 512];  cudaGetSymbolAddress((void**)&wd1, g_wd1);
    bf16 (*wo)[2048 * 1024];  cudaGetSymbolAddress((void**)&wo, g_wo);

    // decoder weight splits (cheap)
    split2_kernel<<<(512 * 256 + 255) / 256, 256>>>(dec0_w, wd0[0], wd0[1], 512 * 256);
    split2_kernel<<<(1024 * 512 + 255) / 256, 256>>>(dec1_w, wd1[0], wd1[1], 1024 * 512);
    split2_kernel<<<(2048 * 1024 + 255) / 256, 256>>>(out_w, wo[0], wo[1], 2048 * 1024);

    // encoder: exact fp32
    launch_enc(x,  enc0_w, enc0_b, h1, 1024, 2048, true);
    launch_enc(h1, enc1_w, enc1_b, h2, 512,  1024, true);
    launch_enc(h2, z_w,    z_b,    z,  256,  512,  false);

    // vector quantization (fp32 distances, plane output)
    cnorm_kernel<<<4, 256>>>(codebook, cn);
    vq_kernel<<<(M_ROWS * 256 / EMB_DIM) / 256, 256>>>(z, codebook, cn, zq[0], zq[1]);

    // decoder: bf16 HMMA, 3-product emulation
    launch_dec<true,  2>(zq[0], zq[1], wd0[0], wd0[1], dec0_b, nullptr, d1[0], d1[1], 512, 256);
    launch_dec<true,  2>(d1[0], d1[1], wd1[0], wd1[1], dec1_b, nullptr, d2[0], d2[1], 1024, 512);
    launch_dec<false, 0>(d2[0], d2[1], wo[0], wo[1],  out_b,  out, nullptr, nullptr, 2048, 1024);
}

// round 7
// speedup vs baseline: 1.3802x; 1.2024x over previous
#include <cuda_runtime.h>
#include <cuda_bf16.h>
#include <cstdint>

// ===========================================================================
// VQ-VAE forward on GB300:
//   encoder  : exact fp32 SIMT GEMMs (argmin-critical; proven, DO NOT TOUCH)
//   VQ       : fp32 distances (proven), outputs zq as 2 bf16 planes
//   decoder  : bf16 HMMA, 2-plane / 3-product (hh+hm+mh), fused 4-tile loads:
//              all 3 products computed per k-chunk (no redundant reloads),
//              merged accumulator, 2 CTAs/SM.
// ===========================================================================

#define M_ROWS 8192
#define EMB_NUM 1024
#define EMB_DIM 64

typedef unsigned long long u64;
typedef __nv_bfloat16 bf16;

// ---------------------------------------------------------------------------
// Static device scratch (allocation-free rule)
// ---------------------------------------------------------------------------
__device__ float g_h1[8192 * 1024];
__device__ float g_h2[8192 * 512];
__device__ float g_z [8192 * 256];
__device__ float g_cn[EMB_NUM];
__device__ bf16 g_zq[2][8192 * 256];
__device__ bf16 g_d1[2][8192 * 512];
__device__ bf16 g_d2[2][8192 * 1024];
__device__ bf16 g_wd0[2][512 * 256];
__device__ bf16 g_wd1[2][1024 * 512];
__device__ bf16 g_wo[2][2048 * 1024];

// ---------------------------------------------------------------------------
// PTX helpers
// ---------------------------------------------------------------------------
__device__ __forceinline__ uint32_t smem_u32(const void* p) {
    uint32_t a;
    asm("{ .reg .u64 t; cvta.to.shared.u64 t, %1; cvt.u32.u64 %0, t; }" : "=r"(a) : "l"(p));
    return a;
}
__device__ __forceinline__ void cp16(uint32_t dst, const void* src) {
    asm volatile("cp.async.cg.shared.global [%0], [%1], 16;" :: "r"(dst), "l"(src));
}
#define CP_COMMIT() asm volatile("cp.async.commit_group;" ::: "memory")
#define CP_WAIT0()  asm volatile("cp.async.wait_group 0;" ::: "memory")

__device__ __forceinline__ void ldm_x4(uint32_t r[4], uint32_t addr) {
    asm volatile("ldmatrix.sync.aligned.m8n8.x4.shared.b16 {%0,%1,%2,%3}, [%4];"
                 : "=r"(r[0]), "=r"(r[1]), "=r"(r[2]), "=r"(r[3]) : "r"(addr));
}
__device__ __forceinline__ void mma_bf16(float* d, const uint32_t* a, uint32_t b0, uint32_t b1) {
    asm volatile(
        "mma.sync.aligned.m16n8k16.row.col.f32.bf16.bf16.f32 "
        "{%0,%1,%2,%3}, {%4,%5,%6,%7}, {%8,%9}, {%0,%1,%2,%3};"
        : "+f"(d[0]), "+f"(d[1]), "+f"(d[2]), "+f"(d[3])
        : "r"(a[0]), "r"(a[1]), "r"(a[2]), "r"(a[3]), "r"(b0), "r"(b1));
}

// ---------------------------------------------------------------------------
// ENCODER: exact fp32 tiled SGEMM (byte-identical to passing round 6)
// ---------------------------------------------------------------------------
template <int BM, int BN, int BK, int TM, int TN, bool RELU>
__global__ __launch_bounds__((BM / TM) * (BN / TN))
void gemm_bias_kernel(const float* __restrict__ A,
                      const float* __restrict__ W,
                      const float* __restrict__ bias,
                      float* __restrict__ C,
                      int M, int N, int K) {
    constexpr int THREADS = (BM / TM) * (BN / TN);
    constexpr int PAD = 4;
    __shared__ float As[BK][BM + PAD];
    __shared__ float Ws[BK][BN + PAD];

    const int bm = blockIdx.y * BM;
    const int bn = blockIdx.x * BN;
    const int tid = threadIdx.x;
    const int tx = tid % (BN / TN);
    const int ty = tid / (BN / TN);

    float acc[TM][TN];
#pragma unroll
    for (int i = 0; i < TM; i++)
#pragma unroll
        for (int j = 0; j < TN; j++) acc[i][j] = 0.0f;

    for (int k0 = 0; k0 < K; k0 += BK) {
#pragma unroll
        for (int i = tid; i < BM * BK / 4; i += THREADS) {
            int r  = i / (BK / 4);
            int c4 = i % (BK / 4);
            float4 v = *reinterpret_cast<const float4*>(A + (size_t)(bm + r) * K + k0 + c4 * 4);
            As[c4 * 4 + 0][r] = v.x;
            As[c4 * 4 + 1][r] = v.y;
            As[c4 * 4 + 2][r] = v.z;
            As[c4 * 4 + 3][r] = v.w;
        }
#pragma unroll
        for (int i = tid; i < BN * BK / 4; i += THREADS) {
            int r  = i / (BK / 4);
            int c4 = i % (BK / 4);
            float4 v = *reinterpret_cast<const float4*>(W + (size_t)(bn + r) * K + k0 + c4 * 4);
            Ws[c4 * 4 + 0][r] = v.x;
            Ws[c4 * 4 + 1][r] = v.y;
            Ws[c4 * 4 + 2][r] = v.z;
            Ws[c4 * 4 + 3][r] = v.w;
        }
        __syncthreads();

#pragma unroll
        for (int k = 0; k < BK; k++) {
            float a[TM], b[TN];
            *reinterpret_cast<float4*>(&a[0]) = *reinterpret_cast<const float4*>(&As[k][ty * TM + 0]);
            *reinterpret_cast<float4*>(&a[4]) = *reinterpret_cast<const float4*>(&As[k][ty * TM + 4]);
            *reinterpret_cast<float4*>(&b[0]) = *reinterpret_cast<const float4*>(&Ws[k][tx * TN + 0]);
            *reinterpret_cast<float4*>(&b[4]) = *reinterpret_cast<const float4*>(&Ws[k][tx * TN + 4]);
#pragma unroll
            for (int i = 0; i < TM; i++)
#pragma unroll
                for (int j = 0; j < TN; j++)
                    acc[i][j] = fmaf(a[i], b[j], acc[i][j]);
        }
        __syncthreads();
    }

    float bv[TN];
#pragma unroll
    for (int j = 0; j < TN; j++) bv[j] = bias[bn + tx * TN + j];

#pragma unroll
    for (int i = 0; i < TM; i++) {
        int row = bm + ty * TM + i;
        float out[TN];
#pragma unroll
        for (int j = 0; j < TN; j++) {
            float v = acc[i][j] + bv[j];
            if (RELU) v = fmaxf(v, 0.0f);
            out[j] = v;
        }
        float* cptr = C + (size_t)row * N + bn + tx * TN;
        *reinterpret_cast<float4*>(cptr + 0) = *reinterpret_cast<float4*>(&out[0]);
        *reinterpret_cast<float4*>(cptr + 4) = *reinterpret_cast<float4*>(&out[4]);
    }
}

// ---------------------------------------------------------------------------
// DECODER: bf16 HMMA, 2-plane inputs, 3 products (hh, hm, mh) fused per
// k-chunk. 4 tiles loaded once per chunk (A0,A1,B0,B1), 96 MMAs between
// syncs, merged accumulator, 2-stage dynamic-smem double buffer, 2 CTAs/SM.
// ---------------------------------------------------------------------------
#define DEC_TILE_B  10240        // 128 rows * 80 B (40 bf16) per tile
#define DEC_STAGE_B (4 * DEC_TILE_B)
#define DEC_SMEM    (2 * DEC_STAGE_B)   // 81920 bytes

template <bool RELU, int OUTP>
__global__ __launch_bounds__(256, 2)
void gemm_hmma_kernel(const bf16* __restrict__ A0, const bf16* __restrict__ A1,
                      const bf16* __restrict__ B0, const bf16* __restrict__ B1,
                      const float* __restrict__ bias,
                      float* __restrict__ Cf,
                      bf16* __restrict__ Ch, bf16* __restrict__ Cm,
                      int N, int K) {
    extern __shared__ char dsm[];
    const uint32_t su = smem_u32(dsm);

    const int tid = threadIdx.x;
    const int wid = tid >> 5, lane = tid & 31;
    const int wm = wid >> 2, wn = wid & 3;
    const int bn = blockIdx.x * 128, bm = blockIdx.y * 128;
    const int KC = K >> 5;

    const bf16* P[4] = { A0 + (size_t)bm * K, A1 + (size_t)bm * K,
                         B0 + (size_t)bn * K, B1 + (size_t)bn * K };

    float acc[4][4][4];
#pragma unroll
    for (int i = 0; i < 4; i++)
#pragma unroll
        for (int j = 0; j < 4; j++)
#pragma unroll
            for (int q = 0; q < 4; q++) acc[i][j][q] = 0.0f;

    auto load_chunk = [&](int stage, int k0) {
#pragma unroll
        for (int t = 0; t < 4; t++) {
            const bf16* src = P[t];
#pragma unroll
            for (int j = 0; j < 2; j++) {
                int ch = j * 256 + tid;            // 0..511
                int r = ch >> 2, cc = ch & 3;      // row, 16B group
                uint32_t off = (uint32_t)((stage * 4 + t) * DEC_TILE_B + r * 80 + cc * 16);
                cp16(su + off, src + (size_t)r * K + k0 + cc * 8);
            }
        }
        CP_COMMIT();
    };

    load_chunk(0, 0);

    const int tA[3] = {0, 0, 1};
    const int tB[3] = {2, 3, 2};

    for (int c = 0; c < KC; c++) {
        CP_WAIT0();
        __syncthreads();
        if (c + 1 < KC) load_chunk((c + 1) & 1, (c + 1) << 5);

        const int stage = c & 1;
#pragma unroll
        for (int p = 0; p < 3; p++) {
            const uint32_t baseA = su + (uint32_t)((stage * 4 + tA[p]) * DEC_TILE_B);
            const uint32_t baseB = su + (uint32_t)((stage * 4 + tB[p]) * DEC_TILE_B);
#pragma unroll
            for (int ks = 0; ks < 2; ks++) {
                uint32_t af[4][4], bg[2][4];
#pragma unroll
                for (int mt = 0; mt < 4; mt++) {
                    uint32_t addr = baseA + (uint32_t)((wm * 64 + mt * 16 + ((lane >> 3) & 1) * 8 + (lane & 7)) * 80
                                                       + (ks * 16 + (lane >> 4) * 8) * 2);
                    ldm_x4(af[mt], addr);
                }
#pragma unroll
                for (int np = 0; np < 2; np++) {
                    uint32_t addr = baseB + (uint32_t)((wn * 32 + np * 16 + ((lane >> 4) & 1) * 8 + (lane & 7)) * 80
                                                       + (ks * 16 + ((lane >> 3) & 1) * 8) * 2);
                    ldm_x4(bg[np], addr);
                }
#pragma unroll
                for (int mt = 0; mt < 4; mt++)
#pragma unroll
                    for (int nt = 0; nt < 4; nt++)
                        mma_bf16(acc[mt][nt], af[mt], bg[nt >> 1][(nt & 1) * 2], bg[nt >> 1][(nt & 1) * 2 + 1]);
            }
        }
        __syncthreads();
    }

#pragma unroll
    for (int mt = 0; mt < 4; mt++) {
#pragma unroll
        for (int nt = 0; nt < 4; nt++) {
            const int r0 = bm + wm * 64 + mt * 16 + (lane >> 2);
            const int c0 = bn + wn * 32 + nt * 8 + (lane & 3) * 2;
            const float bv0 = bias[c0], bv1 = bias[c0 + 1];
#pragma unroll
            for (int h = 0; h < 2; h++) {
                const int r = r0 + h * 8;
                float v0 = acc[mt][nt][h * 2 + 0] + bv0;
                float v1 = acc[mt][nt][h * 2 + 1] + bv1;
                if (RELU) { v0 = fmaxf(v0, 0.0f); v1 = fmaxf(v1, 0.0f); }
                const size_t o = (size_t)r * N + c0;
                if (OUTP == 0) {
                    *reinterpret_cast<float2*>(Cf + o) = make_float2(v0, v1);
                } else {
                    bf16 h0 = __float2bfloat16(v0), h1v = __float2bfloat16(v1);
                    float r0f = v0 - __bfloat162float(h0);
                    float r1f = v1 - __bfloat162float(h1v);
                    __nv_bfloat162 hp; hp.x = h0; hp.y = h1v;
                    __nv_bfloat162 mp; mp.x = __float2bfloat16(r0f); mp.y = __float2bfloat16(r1f);
                    *reinterpret_cast<__nv_bfloat162*>(Ch + o) = hp;
                    *reinterpret_cast<__nv_bfloat162*>(Cm + o) = mp;
                }
            }
        }
    }
}

// ---------------------------------------------------------------------------
// fp32 -> 2 bf16 planes (decoder weights)
// ---------------------------------------------------------------------------
__global__ void split2_kernel(const float* __restrict__ src,
                              bf16* __restrict__ h, bf16* __restrict__ m, int n) {
    int i = blockIdx.x * blockDim.x + threadIdx.x;
    if (i < n) {
        float v = src[i];
        bf16 a = __float2bfloat16(v);
        float r1 = v - __bfloat162float(a);
        h[i] = a; m[i] = __float2bfloat16(r1);
    }
}

// ---------------------------------------------------------------------------
// Codebook squared norms
// ---------------------------------------------------------------------------
__global__ void cnorm_kernel(const float* __restrict__ cb, float* __restrict__ cn) {
    int i = blockIdx.x * blockDim.x + threadIdx.x;
    if (i >= EMB_NUM) return;
    const float4* p = reinterpret_cast<const float4*>(cb + (size_t)i * EMB_DIM);
    float s = 0.0f;
#pragma unroll
    for (int d = 0; d < EMB_DIM / 4; d++) {
        float4 v = p[d];
        s += v.x * v.x + v.y * v.y + v.z * v.z + v.w * v.w;
    }
    cn[i] = s;
}

// ---------------------------------------------------------------------------
// VQ: fp32 distances (byte-identical to passing round 6)
// ---------------------------------------------------------------------------
__device__ __forceinline__ u64 pack2f(float lo, float hi) {
    u64 r; asm("mov.b64 %0, {%1, %2};" : "=l"(r) : "f"(lo), "f"(hi)); return r;
}
__device__ __forceinline__ void unpack2f(u64 v, float& lo, float& hi) {
    asm("mov.b64 {%0, %1}, %2;" : "=f"(lo), "=f"(hi) : "l"(v));
}
__device__ __forceinline__ u64 ffma2(u64 a, u64 b, u64 c) {
    u64 d; asm("fma.rn.f32x2 %0, %1, %2, %3;" : "=l"(d) : "l"(a), "l"(b), "l"(c)); return d;
}

__global__ __launch_bounds__(256)
void vq_kernel(const float* __restrict__ z,
               const float* __restrict__ cb,
               const float* __restrict__ cn,
               bf16* __restrict__ qh, bf16* __restrict__ qm) {
    constexpr int CHUNK = 128;
    __shared__ float sc[CHUNK][EMB_DIM];
    __shared__ float scn[CHUNK];

    const int row = blockIdx.x * blockDim.x + threadIdx.x;
    const float* zp = z + (size_t)row * EMB_DIM;

    u64 m2zP[EMB_DIM / 2];
#pragma unroll
    for (int d = 0; d < EMB_DIM / 4; d++) {
        float4 v = reinterpret_cast<const float4*>(zp)[d];
        m2zP[d * 2 + 0] = pack2f(-2.0f * v.x, -2.0f * v.y);
        m2zP[d * 2 + 1] = pack2f(-2.0f * v.z, -2.0f * v.w);
    }

    float best = 3.0e38f;
    int bidx = 0;
    for (int ch = 0; ch < EMB_NUM / CHUNK; ch++) {
        __syncthreads();
        const float4* src = reinterpret_cast<const float4*>(cb + (size_t)ch * CHUNK * EMB_DIM);
        float4* dst = reinterpret_cast<float4*>(&sc[0][0]);
        for (int i = threadIdx.x; i < CHUNK * EMB_DIM / 4; i += 256) dst[i] = src[i];
        if (threadIdx.x < CHUNK) scn[threadIdx.x] = cn[ch * CHUNK + threadIdx.x];
        __syncthreads();

        for (int j = 0; j < CHUNK; j++) {
            u64 sP = 0ull;
#pragma unroll
            for (int d = 0; d < EMB_DIM / 4; d++) {
                float4 cc = reinterpret_cast<const float4*>(&sc[j][0])[d];
                sP = ffma2(pack2f(cc.x, cc.y), m2zP[d * 2 + 0], sP);
                sP = ffma2(pack2f(cc.z, cc.w), m2zP[d * 2 + 1], sP);
            }
            float lo, hi;
            unpack2f(sP, lo, hi);
            float s = scn[j] + lo + hi;
            if (s < best) { best = s; bidx = ch * CHUNK + j; }
        }
    }

    const float* cp = cb + (size_t)bidx * EMB_DIM;
#pragma unroll
    for (int d = 0; d < EMB_DIM; d++) {
        float zz = zp[d];
        float v = zz + (cp[d] - zz);
        bf16 a = __float2bfloat16(v);
        float r1 = v - __bfloat162float(a);
        size_t o = (size_t)row * EMB_DIM + d;
        qh[o] = a; qm[o] = __float2bfloat16(r1);
    }
}

// ---------------------------------------------------------------------------
// Host launch
// ---------------------------------------------------------------------------
static inline void launch_enc(const float* A, const float* W, const float* b,
                              float* C, int N, int K, bool relu) {
    dim3 grid(N / 128, M_ROWS / 128);
    if (relu)
        gemm_bias_kernel<128, 128, 16, 8, 8, true ><<<grid, 256>>>(A, W, b, C, M_ROWS, N, K);
    else
        gemm_bias_kernel<128, 128, 16, 8, 8, false><<<grid, 256>>>(A, W, b, C, M_ROWS, N, K);
}

template <bool RELU, int OUTP>
static inline void launch_dec(const bf16* A0, const bf16* A1,
                              const bf16* B0, const bf16* B1,
                              const float* bias, float* Cf, bf16* Ch, bf16* Cm,
                              int N, int K) {
    cudaFuncSetAttribute(gemm_hmma_kernel<RELU, OUTP>,
                         cudaFuncAttributeMaxDynamicSharedMemorySize, DEC_SMEM);
    dim3 grid(N / 128, M_ROWS / 128);
    gemm_hmma_kernel<RELU, OUTP><<<grid, 256, DEC_SMEM>>>(A0, A1, B0, B1, bias, Cf, Ch, Cm, N, K);
}

extern "C" void kernel_launch(void* const* d_in, const int* in_sizes, int n_in,
                              void* d_out, int out_size) {
    const float* x        = (const float*)d_in[0];
    const float* enc0_w   = (const float*)d_in[1];
    const float* enc0_b   = (const float*)d_in[2];
    const float* enc1_w   = (const float*)d_in[3];
    const float* enc1_b   = (const float*)d_in[4];
    const float* z_w      = (const float*)d_in[5];
    const float* z_b      = (const float*)d_in[6];
    const float* codebook = (const float*)d_in[7];
    const float* dec0_w   = (const float*)d_in[8];
    const float* dec0_b   = (const float*)d_in[9];
    const float* dec1_w   = (const float*)d_in[10];
    const float* dec1_b   = (const float*)d_in[11];
    const float* out_w    = (const float*)d_in[12];
    const float* out_b    = (const float*)d_in[13];
    float* out = (float*)d_out;

    float *h1, *h2, *z, *cn;
    cudaGetSymbolAddress((void**)&h1, g_h1);
    cudaGetSymbolAddress((void**)&h2, g_h2);
    cudaGetSymbolAddress((void**)&z,  g_z);
    cudaGetSymbolAddress((void**)&cn, g_cn);
    bf16 (*zq)[8192 * 256];   cudaGetSymbolAddress((void**)&zq, g_zq);
    bf16 (*d1)[8192 * 512];   cudaGetSymbolAddress((void**)&d1, g_d1);
    bf16 (*d2)[8192 * 1024];  cudaGetSymbolAddress((void**)&d2, g_d2);
    bf16 (*wd0)[512 * 256];   cudaGetSymbolAddress((void**)&wd0, g_wd0);
    bf16 (*wd1)[1024 * 512];  cudaGetSymbolAddress((void**)&wd1, g_wd1);
    bf16 (*wo)[2048 * 1024];  cudaGetSymbolAddress((void**)&wo, g_wo);

    // decoder weight splits (cheap)
    split2_kernel<<<(512 * 256 + 255) / 256, 256>>>(dec0_w, wd0[0], wd0[1], 512 * 256);
    split2_kernel<<<(1024 * 512 + 255) / 256, 256>>>(dec1_w, wd1[0], wd1[1], 1024 * 512);
    split2_kernel<<<(2048 * 1024 + 255) / 256, 256>>>(out_w, wo[0], wo[1], 2048 * 1024);

    // encoder: exact fp32
    launch_enc(x,  enc0_w, enc0_b, h1, 1024, 2048, true);
    launch_enc(h1, enc1_w, enc1_b, h2, 512,  1024, true);
    launch_enc(h2, z_w,    z_b,    z,  256,  512,  false);

    // vector quantization (fp32 distances, plane output)
    cnorm_kernel<<<4, 256>>>(codebook, cn);
    vq_kernel<<<(M_ROWS * 256 / EMB_DIM) / 256, 256>>>(z, codebook, cn, zq[0], zq[1]);

    // decoder: bf16 HMMA, fused 3-product
    launch_dec<true,  2>(zq[0], zq[1], wd0[0], wd0[1], dec0_b, nullptr, d1[0], d1[1], 512, 256);
    launch_dec<true,  2>(d1[0], d1[1], wd1[0], wd1[1], dec1_b, nullptr, d2[0], d2[1], 1024, 512);
    launch_dec<false, 0>(d2[0], d2[1], wo[0], wo[1],  out_b,  out, nullptr, nullptr, 2048, 1024);
}